// round 15
// baseline (speedup 1.0000x reference)
#include <cuda_runtime.h>
#include <cstdint>
#include <math.h>

#define BB 64
#define TT 512
#define DD 256
#define HH 256
#define NTHR 256
#define NBLK 128

// ---------------- device scratch (static allocation, allowed) ----------------
__device__ float g_xt[2][TT][4][DD][32];    // [dir][t][bgrp][k][b-dup]   (128 MB)
__device__ float g_hb[2][2][4][HH][32];     // [dir][phase][bgrp][n][b-dup]
__device__ int   g_flag[2][4][32][32];      // [chain][bgrp][nc][pad] one 128B line each
__device__ unsigned g_bcnt, g_bsns;         // global barrier (self-stable)

// ---- fast gate math (|rel err| ~1e-6, saturation-safe) ----
__device__ __forceinline__ float fsig(float v) {
    return __fdividef(1.f, 1.f + __expf(-v));
}
__device__ __forceinline__ float ftanh(float v) {
    return 1.f - __fdividef(2.f, __expf(2.f * v) + 1.f);
}

// ---- packed fp32x2 helpers (sm_100+) ----
__device__ __forceinline__ void fmaf2(unsigned long long& d,
                                      unsigned long long a, unsigned long long b) {
    asm("fma.rn.f32x2 %0, %1, %2, %3;" : "=l"(d) : "l"(a), "l"(b), "l"(d));
}
__device__ __forceinline__ unsigned long long addf2(unsigned long long a,
                                                    unsigned long long b) {
    unsigned long long r;
    asm("add.rn.f32x2 %0, %1, %2;" : "=l"(r) : "l"(a), "l"(b));
    return r;
}
__device__ __forceinline__ void unpack2(unsigned long long v, float& lo, float& hi) {
    asm("mov.b64 {%0, %1}, %2;" : "=f"(lo), "=f"(hi) : "l"(v));
}

// ---- release/acquire flag ops ----
__device__ __forceinline__ void st_release(int* p, int v) {
    asm volatile("st.release.gpu.global.b32 [%0], %1;" :: "l"(p), "r"(v) : "memory");
}
__device__ __forceinline__ int ld_acquire(const int* p) {
    int v;
    asm volatile("ld.acquire.gpu.global.b32 %0, [%1];" : "=r"(v) : "l"(p) : "memory");
    return v;
}

// ---- mbarrier + bulk-copy helpers ----
#define MBAR_INIT(addr, cnt) \
    asm volatile("mbarrier.init.shared.b64 [%0], %1;" :: "r"(addr), "r"(cnt) : "memory")
#define MBAR_EXPECT(addr, bytes) \
    asm volatile("mbarrier.arrive.expect_tx.shared.b64 _, [%0], %1;" \
                 :: "r"(addr), "r"(bytes) : "memory")
__device__ __forceinline__ void mbar_wait(uint32_t addr, uint32_t parity) {
    uint32_t done;
    asm volatile(
        "{\n\t.reg .pred p;\n\t"
        "mbarrier.try_wait.parity.shared.b64 p, [%1], %2;\n\t"
        "selp.b32 %0, 1, 0, p;\n\t}"
        : "=r"(done) : "r"(addr), "r"(parity) : "memory");
    while (!done) {
        asm volatile(
            "{\n\t.reg .pred p;\n\t"
            "mbarrier.try_wait.parity.shared.b64 p, [%1], %2, 0x989680;\n\t"
            "selp.b32 %0, 1, 0, p;\n\t}"
            : "=r"(done) : "r"(addr), "r"(parity) : "memory");
    }
}
__device__ __forceinline__ void bulk_g2s(uint32_t dst, const void* src,
                                         uint32_t bytes, uint32_t mbar) {
    asm volatile(
        "cp.async.bulk.shared::cta.global.mbarrier::complete_tx::bytes "
        "[%0], [%1], %2, [%3];"
        :: "r"(dst), "l"(src), "r"(bytes), "r"(mbar) : "memory");
}

__device__ __forceinline__ uint32_t smem_u32(const void* p) {
    uint32_t a;
    asm("{ .reg .u64 t; cvta.to.shared.u64 t, %1; cvt.u32.u64 %0, t; }"
        : "=r"(a) : "l"(p));
    return a;
}

__device__ __forceinline__ void global_barrier(int tid) {
    __syncthreads();
    if (tid == 0) {
        unsigned s0 = *((volatile unsigned*)&g_bsns);
        __threadfence();
        unsigned a = atomicAdd(&g_bcnt, 1u);
        if (a == NBLK - 1) {
            atomicExch(&g_bcnt, 0u);
            __threadfence();
            atomicExch(&g_bsns, s0 ^ 1u);
        } else {
            while (*((volatile unsigned*)&g_bsns) == s0) {}
        }
        __threadfence();
    }
    __syncthreads();
}

// SMEM float offsets
#define WT_F    0                         // [2][512][32] weights (both dirs) 128 KB
#define BUFA_F  32768                     // [256][32] x-tile buffer, 32 KB
#define BUFB_F  40960                     // [256][32] h-tile buffer, 32 KB
#define RED_F   49152                     // u64[8][8][2][16] = 16 KB
#define BSV_F   53248                     // [2][32]
#define SLEN_F  53312                     // [64]
#define MB_F    53376                     // 2 x u64 mbarriers
#define SMEM_FLOATS (MB_F + 4)

// Inner GEMM: N k-steps, thread tile = 1 row-group (4 gates) x 4 batches.
// Per k: 1 w LDS.128 + 2 h LDS.128 + 8 FFMA2 = 16 MACs.
// acc[pr*4 + bidx]: pr 0=(i,f) 1=(g,o); bidx = batch within thread quad.
template <int N>
__device__ __forceinline__ void gemm8(unsigned long long* acc,
                                      const float* __restrict__ hp,
                                      const float* __restrict__ wp) {
    #pragma unroll 8
    for (int kk = 0; kk < N; ++kk) {
        ulonglong2 w  = *(const ulonglong2*)(wp + kk * 32);      // (i,f),(g,o)
        ulonglong2 hA = *(const ulonglong2*)(hp + kk * 32);      // (b0,b0),(b1,b1)
        ulonglong2 hB = *(const ulonglong2*)(hp + kk * 32 + 4);  // (b2,b2),(b3,b3)
        fmaf2(acc[0], w.x, hA.x); fmaf2(acc[1], w.x, hA.y);
        fmaf2(acc[2], w.x, hB.x); fmaf2(acc[3], w.x, hB.y);
        fmaf2(acc[4], w.y, hA.x); fmaf2(acc[5], w.y, hA.y);
        fmaf2(acc[6], w.y, hB.x); fmaf2(acc[7], w.y, hB.y);
    }
}

extern "C" __global__ void __launch_bounds__(NTHR, 1)
bilstm_kernel(const float* __restrict__ x,
              const int*   __restrict__ lens,
              const float* __restrict__ Wih_f, const float* __restrict__ Whh_f,
              const float* __restrict__ bih_f, const float* __restrict__ bhh_f,
              const float* __restrict__ Wih_b, const float* __restrict__ Whh_b,
              const float* __restrict__ bih_b, const float* __restrict__ bhh_b,
              float* __restrict__ out)
{
    extern __shared__ float smem[];
    float* wt   = smem + WT_F;          // [dir][k 512][row 32], row = nl*4+gate
    float* bufA = smem + BUFA_F;        // x tiles (rotating)
    float* bufB = smem + BUFB_F;        // h tiles (rotating)
    unsigned long long* red = (unsigned long long*)(smem + RED_F);
    float* bsv  = smem + BSV_F;         // [dir][32] bih+bhh
    int*   slen = (int*)(smem + SLEN_F);
    float* tile = wt;                   // prologue transpose tile [256][65] (alias)

    const uint32_t bufA_b = smem_u32(bufA);
    const uint32_t bufB_b = smem_u32(bufB);
    const uint32_t mbA = smem_u32(smem + MB_F);
    const uint32_t mbB = mbA + 8;

    const int tid  = threadIdx.x;
    const int bgrp = blockIdx.x >> 5;   // 0..3 : 16-batch group
    const int nc   = blockIdx.x & 31;   // 0..31: 8-hidden-dim chunk (both dirs)

    // ---------------- prologue ----------------
    if (tid < BB) slen[tid] = lens[tid];
    __syncthreads();

    // x transpose+dup via smem tile: prologue role dir_pro = bid>>6 (unchanged R14)
    {
        const int dir_pro = blockIdx.x >> 6;
        const int idx64 = blockIdx.x & 63;
        const int bq  = tid >> 2;
        const int kq4 = tid & 3;
        for (int s = idx64; s < TT; s += 64) {
            int t;
            if (dir_pro == 0) t = s;
            else              t = TT - 1 - ((TT - slen[bq] + s) % TT);
            const float* xrow = x + ((size_t)bq * TT + t) * DD;
            #pragma unroll
            for (int kk = 0; kk < 16; ++kk) {
                int k0 = kq4 * 64 + kk * 4;
                float4 v = *(const float4*)(xrow + k0);
                tile[(k0 + 0) * 65 + bq] = v.x;
                tile[(k0 + 1) * 65 + bq] = v.y;
                tile[(k0 + 2) * 65 + bq] = v.z;
                tile[(k0 + 3) * 65 + bq] = v.w;
            }
            __syncthreads();
            const int k2 = tid;
            #pragma unroll
            for (int bg4 = 0; bg4 < 4; ++bg4) {
                float* dst = &g_xt[dir_pro][s][bg4][k2][0];
                #pragma unroll
                for (int blp = 0; blp < 8; ++blp) {
                    float f0 = tile[k2 * 65 + bg4 * 16 + blp * 2 + 0];
                    float f1 = tile[k2 * 65 + bg4 * 16 + blp * 2 + 1];
                    float4 w; w.x = f0; w.y = f0; w.z = f1; w.w = f1;
                    *(float4*)(dst + blp * 4) = w;
                }
            }
            __syncthreads();
        }
    }

    // weight slices (both dirs): wt[d][k][nl*4+g], rows j = g*HH + nc*8 + nl
    for (int idx = tid; idx < 2 * 512 * 32; idx += NTHR) {
        int d   = idx >> 14;
        int r   = idx & 16383;
        int k   = r >> 5;
        int row = r & 31;
        int nl = row >> 2, g = row & 3;
        int j = g * HH + nc * 8 + nl;
        const float* Wi = d ? Wih_b : Wih_f;
        const float* Wh = d ? Whh_b : Whh_f;
        wt[idx] = (k < DD) ? Wi[(size_t)j * DD + k] : Wh[(size_t)j * HH + (k - DD)];
    }
    if (tid < 64) {
        int d = tid >> 5, row = tid & 31;
        int nl = row >> 2, g = row & 3;
        int j = g * HH + nc * 8 + nl;
        const float* bi = d ? bih_b : bih_f;
        const float* bh = d ? bhh_b : bhh_f;
        bsv[tid] = bi[j] + bh[j];
    }
    // zero all h buffers (cooperative across all blocks)
    {
        float* hb = &g_hb[0][0][0][0][0];
        const int total = 2 * 2 * 4 * HH * 32;
        for (int i = blockIdx.x * NTHR + tid; i < total; i += NBLK * NTHR) hb[i] = 0.f;
    }
    if (tid == 0) {
        MBAR_INIT(mbA, 1);
        MBAR_INIT(mbB, 1);
    }
    __syncthreads();
    if (tid == 0) {
        st_release(&g_flag[0][bgrp][nc][0], 1);   // h0(0) ready
        st_release(&g_flag[1][bgrp][nc][0], 1);   // h1(0) ready
    }

    global_barrier(tid);

    // prime x0(0) -> bufA
    if (tid == 0) {
        MBAR_EXPECT(mbA, 32768u);
        bulk_g2s(bufA_b, &g_xt[0][0][bgrp][0][0], 32768u, mbA);
    }

    // ---------------- dual-chain recurrence ----------------
    // gemm map: warp kq8 = k-slice (32 k per half); lane -> (nl 0..7, bgq 0..3)
    const int kq8  = tid >> 5;
    const int lane = tid & 31;
    const int nl   = lane >> 2;
    const int bgq  = lane & 3;
    // epilogue map: threads 0-127 own chain-0 cells, 128-255 chain-1
    const int et  = tid & 127;
    const int enl = et >> 4;            // hidden dim 0..7
    const int ebl = et & 15;            // batch 0..15
    const int n_out = nc * 8 + enl;
    const int myb = bgrp * 16 + ebl;
    const int L   = slen[myb];

    const float* hpA = bufA + (kq8 * 32) * 32 + bgq * 8;
    const float* hpB = bufB + (kq8 * 32) * 32 + bgq * 8;
    const float* wp_x0 = wt + 0     + (kq8 * 32) * 32 + nl * 4;
    const float* wp_h0 = wt + 0     + (DD + kq8 * 32) * 32 + nl * 4;
    const float* wp_x1 = wt + 16384 + (kq8 * 32) * 32 + nl * 4;
    const float* wp_h1 = wt + 16384 + (DD + kq8 * 32) * 32 + nl * 4;

    float cth = 0.f;                    // chain-(tid>>7) cell state

    for (int s = 0; s < TT; ++s) {
        const int p = s & 1;

        // ===== chain 0 (forward dir) =====
        // warp 7: poll flag0 then issue h0(s) -> bufB (overlaps x0-gemm)
        if (kq8 == 7) {
            const int* fp = &g_flag[0][bgrp][lane][0];
            int v = ld_acquire(fp);
            while (v < s + 1) { __nanosleep(20); v = ld_acquire(fp); }
            __syncwarp();
            if (lane == 0) {
                MBAR_EXPECT(mbB, 32768u);
                bulk_g2s(bufB_b, &g_hb[0][p][bgrp][0][0], 32768u, mbB);
            }
        }

        unsigned long long acc[8];
        #pragma unroll
        for (int i = 0; i < 8; ++i) acc[i] = 0ull;

        mbar_wait(mbA, 0);                  // x0(s) in bufA
        gemm8<32>(acc, hpA, wp_x0);
        mbar_wait(mbB, 0);                  // h0(s) in bufB
        gemm8<32>(acc, hpB, wp_h0);

        // publish red0
        #pragma unroll
        for (int pr = 0; pr < 2; ++pr)
            #pragma unroll
            for (int bp = 0; bp < 2; ++bp) {
                ulonglong2 v;
                v.x = acc[pr * 4 + bp * 2 + 0];
                v.y = acc[pr * 4 + bp * 2 + 1];
                *(ulonglong2*)&red[((kq8 * 8 + nl) * 2 + pr) * 16 + bgq * 4 + bp * 2] = v;
            }
        __syncthreads();                    // S2: red0 ready; bufA free

        // issue x1(s) -> bufA (window: epi0 + S3)
        if (tid == 0) {
            MBAR_EXPECT(mbA, 32768u);
            bulk_g2s(bufA_b, &g_xt[1][s][bgrp][0][0], 32768u, mbA);
        }

        // epilogue chain 0 (threads 0-127)
        float hval0 = 0.f;
        if (tid < 128) {
            unsigned long long s01 = 0ull, s23 = 0ull;
            #pragma unroll
            for (int q = 0; q < 8; ++q) {
                s01 = addf2(s01, red[((q * 8 + enl) * 2 + 0) * 16 + ebl]);
                s23 = addf2(s23, red[((q * 8 + enl) * 2 + 1) * 16 + ebl]);
            }
            float pi, pf, pg, po;
            unpack2(s01, pi, pf);
            unpack2(s23, pg, po);
            pi += bsv[enl * 4 + 0]; pf += bsv[enl * 4 + 1];
            pg += bsv[enl * 4 + 2]; po += bsv[enl * 4 + 3];
            float si = fsig(pi), sf = fsig(pf), tg = ftanh(pg), so = fsig(po);
            cth = sf * cth + si * tg;
            hval0 = so * ftanh(cth);
            float2 hd; hd.x = hval0; hd.y = hval0;
            *(float2*)&g_hb[0][p ^ 1][bgrp][n_out][ebl * 2] = hd;
        }
        __syncthreads();                    // S3: h0(s+1) stores done
        if (tid == 0) st_release(&g_flag[0][bgrp][nc][0], s + 2);
        if (tid < 128 && s < L)
            out[((size_t)myb * TT + s) * (2 * HH) + n_out] = hval0;

        // ===== chain 1 (backward dir) =====
        // warp 6: poll flag1 then issue h1(s) -> bufB (overlaps x1-gemm)
        if (kq8 == 6) {
            const int* fp = &g_flag[1][bgrp][lane][0];
            int v = ld_acquire(fp);
            while (v < s + 1) { __nanosleep(20); v = ld_acquire(fp); }
            __syncwarp();
            if (lane == 0) {
                MBAR_EXPECT(mbB, 32768u);
                bulk_g2s(bufB_b, &g_hb[1][p][bgrp][0][0], 32768u, mbB);
            }
        }

        #pragma unroll
        for (int i = 0; i < 8; ++i) acc[i] = 0ull;

        mbar_wait(mbA, 1);                  // x1(s) in bufA
        gemm8<32>(acc, hpA, wp_x1);
        mbar_wait(mbB, 1);                  // h1(s) in bufB
        gemm8<32>(acc, hpB, wp_h1);

        // publish red1
        #pragma unroll
        for (int pr = 0; pr < 2; ++pr)
            #pragma unroll
            for (int bp = 0; bp < 2; ++bp) {
                ulonglong2 v;
                v.x = acc[pr * 4 + bp * 2 + 0];
                v.y = acc[pr * 4 + bp * 2 + 1];
                *(ulonglong2*)&red[((kq8 * 8 + nl) * 2 + pr) * 16 + bgq * 4 + bp * 2] = v;
            }
        __syncthreads();                    // S4: red1 ready; bufA free

        // issue x0(s+1) -> bufA (window: epi1 + S5 + next-step top)
        if (tid == 0 && s + 1 < TT) {
            MBAR_EXPECT(mbA, 32768u);
            bulk_g2s(bufA_b, &g_xt[0][s + 1][bgrp][0][0], 32768u, mbA);
        }

        // epilogue chain 1 (threads 128-255)
        float hval1 = 0.f;
        if (tid >= 128) {
            unsigned long long s01 = 0ull, s23 = 0ull;
            #pragma unroll
            for (int q = 0; q < 8; ++q) {
                s01 = addf2(s01, red[((q * 8 + enl) * 2 + 0) * 16 + ebl]);
                s23 = addf2(s23, red[((q * 8 + enl) * 2 + 1) * 16 + ebl]);
            }
            float pi, pf, pg, po;
            unpack2(s01, pi, pf);
            unpack2(s23, pg, po);
            pi += bsv[32 + enl * 4 + 0]; pf += bsv[32 + enl * 4 + 1];
            pg += bsv[32 + enl * 4 + 2]; po += bsv[32 + enl * 4 + 3];
            float si = fsig(pi), sf = fsig(pf), tg = ftanh(pg), so = fsig(po);
            cth = sf * cth + si * tg;
            hval1 = so * ftanh(cth);
            float2 hd; hd.x = hval1; hd.y = hval1;
            *(float2*)&g_hb[1][p ^ 1][bgrp][n_out][ebl * 2] = hd;
        }
        __syncthreads();                    // S5: h1(s+1) stores done
        if (tid == 0) st_release(&g_flag[1][bgrp][nc][0], s + 2);
        if (tid >= 128 && s < L)
            out[((size_t)myb * TT + (L - 1 - s)) * (2 * HH) + HH + n_out] = hval1;
    }

    // final barrier, then reset flags for the next graph replay
    global_barrier(tid);
    if (tid == 0) {
        *((volatile int*)&g_flag[0][bgrp][nc][0]) = 0;
        *((volatile int*)&g_flag[1][bgrp][nc][0]) = 0;
    }
}

extern "C" void kernel_launch(void* const* d_in, const int* in_sizes, int n_in,
                              void* d_out, int out_size) {
    const float* x     = (const float*)d_in[0];
    const int*   lens  = (const int*)  d_in[1];
    const float* Wih_f = (const float*)d_in[2];
    const float* Whh_f = (const float*)d_in[3];
    const float* bih_f = (const float*)d_in[4];
    const float* bhh_f = (const float*)d_in[5];
    const float* Wih_b = (const float*)d_in[6];
    const float* Whh_b = (const float*)d_in[7];
    const float* bih_b = (const float*)d_in[8];
    const float* bhh_b = (const float*)d_in[9];
    float* out = (float*)d_out;

    // zero the padded/masked region (output beyond input_length must be 0)
    cudaMemsetAsync(out, 0, (size_t)out_size * sizeof(float), 0);

    const size_t smem_bytes = (size_t)SMEM_FLOATS * sizeof(float);
    cudaFuncSetAttribute(bilstm_kernel,
                         cudaFuncAttributeMaxDynamicSharedMemorySize, (int)smem_bytes);

    bilstm_kernel<<<NBLK, NTHR, smem_bytes>>>(x, lens, Wih_f, Whh_f, bih_f, bhh_f,
                                              Wih_b, Whh_b, bih_b, bhh_b, out);
}

// round 16
// speedup vs baseline: 1.9195x; 1.9195x over previous
#include <cuda_runtime.h>
#include <cstdint>
#include <math.h>

#define BB 64
#define TT 512
#define DD 256
#define HH 256
#define KK 512
#define NTHR 256
#define NBLK 128
#define NB_N 16        // hidden dims per block
#define NB_B 16        // batches per block
#define NGRP 8         // sync groups (dir x bgrp)
#define GRPBLK 16      // blocks per sync group

// ---------------- device scratch (static allocation, allowed) ----------------
__device__ float g_xt[2][TT][4][DD][NB_B];      // [dir][t][bgrp][k][b] non-dup (64 MB)
__device__ float g_hb[2][2][4][HH][NB_B];       // [dir][phase][bgrp][n][b] non-dup
__device__ int      g_flag[NGRP][GRPBLK][32];   // step flags, one 128B line each
__device__ unsigned g_bcnt, g_bsns;             // global barrier (self-stable)

// ---- fast gate math (|rel err| ~1e-6, saturation-safe) ----
__device__ __forceinline__ float fsig(float v) {
    return __fdividef(1.f, 1.f + __expf(-v));
}
__device__ __forceinline__ float ftanh(float v) {
    return 1.f - __fdividef(2.f, __expf(2.f * v) + 1.f);
}

// ---- packed fp32x2 helpers (sm_100+) ----
__device__ __forceinline__ void fmaf2(unsigned long long& d,
                                      unsigned long long a, unsigned long long b) {
    asm("fma.rn.f32x2 %0, %1, %2, %3;" : "=l"(d) : "l"(a), "l"(b), "l"(d));
}
__device__ __forceinline__ unsigned long long addf2(unsigned long long a,
                                                    unsigned long long b) {
    unsigned long long r;
    asm("add.rn.f32x2 %0, %1, %2;" : "=l"(r) : "l"(a), "l"(b));
    return r;
}
__device__ __forceinline__ void unpack2(unsigned long long v, float& lo, float& hi) {
    asm("mov.b64 {%0, %1}, %2;" : "=f"(lo), "=f"(hi) : "l"(v));
}
__device__ __forceinline__ unsigned long long pack2(float lo, float hi) {
    unsigned long long r;
    asm("mov.b64 %0, {%1, %2};" : "=l"(r) : "f"(lo), "f"(hi));
    return r;
}

// ---- release/acquire flag ops ----
__device__ __forceinline__ void st_release(int* p, int v) {
    asm volatile("st.release.gpu.global.b32 [%0], %1;" :: "l"(p), "r"(v) : "memory");
}
__device__ __forceinline__ int ld_acquire(const int* p) {
    int v;
    asm volatile("ld.acquire.gpu.global.b32 %0, [%1];" : "=r"(v) : "l"(p) : "memory");
    return v;
}

// ---- mbarrier + bulk-copy helpers (single-instruction 16KB transfers) ----
#define MBAR_INIT(addr, cnt) \
    asm volatile("mbarrier.init.shared.b64 [%0], %1;" :: "r"(addr), "r"(cnt) : "memory")
#define MBAR_EXPECT(addr, bytes) \
    asm volatile("mbarrier.arrive.expect_tx.shared.b64 _, [%0], %1;" \
                 :: "r"(addr), "r"(bytes) : "memory")
__device__ __forceinline__ void mbar_wait(uint32_t addr, uint32_t parity) {
    uint32_t done;
    asm volatile(
        "{\n\t.reg .pred p;\n\t"
        "mbarrier.try_wait.parity.shared.b64 p, [%1], %2;\n\t"
        "selp.b32 %0, 1, 0, p;\n\t}"
        : "=r"(done) : "r"(addr), "r"(parity) : "memory");
    while (!done) {
        asm volatile(
            "{\n\t.reg .pred p;\n\t"
            "mbarrier.try_wait.parity.shared.b64 p, [%1], %2, 0x989680;\n\t"
            "selp.b32 %0, 1, 0, p;\n\t}"
            : "=r"(done) : "r"(addr), "r"(parity) : "memory");
    }
}
__device__ __forceinline__ void bulk_g2s(uint32_t dst, const void* src,
                                         uint32_t bytes, uint32_t mbar) {
    asm volatile(
        "cp.async.bulk.shared::cta.global.mbarrier::complete_tx::bytes "
        "[%0], [%1], %2, [%3];"
        :: "r"(dst), "l"(src), "r"(bytes), "r"(mbar) : "memory");
}

__device__ __forceinline__ uint32_t smem_u32(const void* p) {
    uint32_t a;
    asm("{ .reg .u64 t; cvta.to.shared.u64 t, %1; cvt.u32.u64 %0, t; }"
        : "=r"(a) : "l"(p));
    return a;
}

__device__ __forceinline__ void global_barrier(int tid) {
    __syncthreads();
    if (tid == 0) {
        unsigned s0 = *((volatile unsigned*)&g_bsns);
        __threadfence();
        unsigned a = atomicAdd(&g_bcnt, 1u);
        if (a == NBLK - 1) {
            atomicExch(&g_bcnt, 0u);
            __threadfence();
            atomicExch(&g_bsns, s0 ^ 1u);
        } else {
            while (*((volatile unsigned*)&g_bsns) == s0) {}
        }
        __threadfence();
    }
    __syncthreads();
}

// SMEM float offsets
#define WT_F    0                       // [512][64]   128 KB (prologue tile aliases)
#define HX_F    (KK * 64)               // [512][16]   32 KB  ([x ; h] non-dup operand)
#define RED_F   (HX_F + KK * 16)        // u64[8][16][2][16] = 32 KB
#define BSV_F   (RED_F + 8192)          // [64]
#define SLEN_F  (BSV_F + 64)            // [64]
#define MB_F    (SLEN_F + 64)           // 2 x u64 mbarriers
#define SMEM_FLOATS (MB_F + 4)

// Inner GEMM: N k-steps, thread tile = 2 row-groups x 4 gates x 4 batches.
// Per k: 3 LDS.128 (w row nl, w row nl+8, 4 batches) + 4 alu pack-movs
// + 16 FFMA2 = 32 MACs.
template <int N>
__device__ __forceinline__ void gemm_phase(unsigned long long* acc,
                                           const float* __restrict__ hp,
                                           const float* __restrict__ wp) {
    #pragma unroll 8
    for (int kk = 0; kk < N; ++kk) {
        ulonglong2 w1 = *(const ulonglong2*)(wp + kk * 64);        // row nl:   (i,f),(g,o)
        ulonglong2 w2 = *(const ulonglong2*)(wp + kk * 64 + 32);   // row nl+8: (i,f),(g,o)
        float4 h4 = *(const float4*)(hp + kk * 16);                // b0..b3
        unsigned long long hA0 = pack2(h4.x, h4.x);
        unsigned long long hA1 = pack2(h4.y, h4.y);
        unsigned long long hB0 = pack2(h4.z, h4.z);
        unsigned long long hB1 = pack2(h4.w, h4.w);
        fmaf2(acc[0],  w1.x, hA0); fmaf2(acc[1],  w1.x, hA1);
        fmaf2(acc[2],  w1.x, hB0); fmaf2(acc[3],  w1.x, hB1);
        fmaf2(acc[4],  w1.y, hA0); fmaf2(acc[5],  w1.y, hA1);
        fmaf2(acc[6],  w1.y, hB0); fmaf2(acc[7],  w1.y, hB1);
        fmaf2(acc[8],  w2.x, hA0); fmaf2(acc[9],  w2.x, hA1);
        fmaf2(acc[10], w2.x, hB0); fmaf2(acc[11], w2.x, hB1);
        fmaf2(acc[12], w2.y, hA0); fmaf2(acc[13], w2.y, hA1);
        fmaf2(acc[14], w2.y, hB0); fmaf2(acc[15], w2.y, hB1);
    }
}

extern "C" __global__ void __launch_bounds__(NTHR, 1)
bilstm_kernel(const float* __restrict__ x,
              const int*   __restrict__ lens,
              const float* __restrict__ Wih_f, const float* __restrict__ Whh_f,
              const float* __restrict__ bih_f, const float* __restrict__ bhh_f,
              const float* __restrict__ Wih_b, const float* __restrict__ Whh_b,
              const float* __restrict__ bih_b, const float* __restrict__ bhh_b,
              float* __restrict__ out)
{
    extern __shared__ float smem[];
    float* wt = smem + WT_F;                // [512][64] weight rows, r = nl*4+g
    float* hx = smem + HX_F;                // [512][16] staged [x ; h], non-dup
    unsigned long long* red = (unsigned long long*)(smem + RED_F);
    float* bsv  = smem + BSV_F;
    int*   slen = (int*)(smem + SLEN_F);
    float* tile = wt;                       // prologue transpose tile [256][65]

    const uint32_t hx_b  = smem_u32(hx);
    const uint32_t mbx_b = smem_u32(smem + MB_F);       // x-tile mbarrier
    const uint32_t mbh_b = mbx_b + 8;                   // h-tile mbarrier

    const int tid  = threadIdx.x;
    const int dir  = blockIdx.x >> 6;
    const int bgrp = (blockIdx.x >> 4) & 3;
    const int nc   = blockIdx.x & 15;
    const int gid  = blockIdx.x >> 4;

    const float* Wih = dir ? Wih_b : Wih_f;
    const float* Whh = dir ? Whh_b : Whh_f;
    const float* bih = dir ? bih_b : bih_f;
    const float* bhh = dir ? bhh_b : bhh_f;

    // ---------------- prologue ----------------
    if (tid < BB) slen[tid] = lens[tid];
    __syncthreads();

    // transpose x -> g_xt[dir][t][bgrp][k][16] (non-dup), blocks stride-64 over t
    {
        const int idx64 = blockIdx.x & 63;
        const int bq  = tid >> 2;
        const int kq4 = tid & 3;
        for (int s = idx64; s < TT; s += 64) {
            int t;
            if (dir == 0) t = s;
            else          t = TT - 1 - ((TT - slen[bq] + s) % TT);
            const float* xrow = x + ((size_t)bq * TT + t) * DD;
            #pragma unroll
            for (int kk = 0; kk < 16; ++kk) {
                int k0 = kq4 * 64 + kk * 4;
                float4 v = *(const float4*)(xrow + k0);
                tile[(k0 + 0) * 65 + bq] = v.x;
                tile[(k0 + 1) * 65 + bq] = v.y;
                tile[(k0 + 2) * 65 + bq] = v.z;
                tile[(k0 + 3) * 65 + bq] = v.w;
            }
            __syncthreads();
            const int k2 = tid;
            #pragma unroll
            for (int bg4 = 0; bg4 < 4; ++bg4) {
                float* dst = &g_xt[dir][s][bg4][k2][0];
                #pragma unroll
                for (int q = 0; q < 4; ++q) {
                    float4 o;
                    o.x = tile[k2 * 65 + bg4 * 16 + q * 4 + 0];
                    o.y = tile[k2 * 65 + bg4 * 16 + q * 4 + 1];
                    o.z = tile[k2 * 65 + bg4 * 16 + q * 4 + 2];
                    o.w = tile[k2 * 65 + bg4 * 16 + q * 4 + 3];
                    *(float4*)(dst + q * 4) = o;
                }
            }
            __syncthreads();
        }
    }

    // weight slice: wt[k][r], r = nl*4 + g (gate order i,f,g,o)
    for (int idx = tid; idx < KK * 64; idx += NTHR) {
        int k = idx >> 6, r = idx & 63;
        int nl = r >> 2, g = r & 3;
        int j = g * HH + nc * NB_N + nl;
        wt[idx] = (k < DD) ? Wih[(size_t)j * DD + k] : Whh[(size_t)j * HH + (k - DD)];
    }
    if (tid < 64) {
        int nl = tid >> 2, g = tid & 3;
        int j = g * HH + nc * NB_N + nl;
        bsv[tid] = bih[j] + bhh[j];
    }
    // zero all h buffers (cooperative across all blocks)
    {
        float* hb = &g_hb[0][0][0][0][0];
        const int total = 2 * 2 * 4 * HH * NB_B;
        for (int i = blockIdx.x * NTHR + tid; i < total; i += NBLK * NTHR) hb[i] = 0.f;
    }
    if (tid == 0) {
        MBAR_INIT(mbx_b, 1);
        MBAR_INIT(mbh_b, 1);
    }
    __syncthreads();
    if (tid == 0) st_release(&g_flag[gid][nc][0], 1);   // h(0) ready

    global_barrier(tid);

    // prime x(0): single bulk copy, 16 KB
    if (tid == 0) {
        MBAR_EXPECT(mbx_b, 16384u);
        bulk_g2s(hx_b, &g_xt[dir][0][bgrp][0][0], 16384u, mbx_b);
    }

    // ---------------- recurrence ----------------
    // gemm map: warp = k-group (kq8 = 0..7, 32 k each half); lane -> (nl, bgq)
    const int kq8 = tid >> 5;
    const int lane = tid & 31;
    const int nl  = lane >> 2;
    const int bgq = lane & 3;
    // epilogue map: one (n, b) cell per thread
    const int nl2 = tid >> 4;
    const int bl  = tid & 15;
    const int n   = nc * NB_N + nl2;
    const int myb = bgrp * NB_B + bl;
    const int L   = slen[myb];

    const float* wp_x = wt + (kq8 * 32) * 64 + nl * 4;
    const float* hp_x = hx + (kq8 * 32) * 16 + bgq * 4;
    const float* wp_h = wt + (DD + kq8 * 32) * 64 + nl * 4;
    const float* hp_h = hx + (DD + kq8 * 32) * 16 + bgq * 4;

    float cth = 0.f;
    int p = 0;

    for (int s = 0; s < TT; ++s) {
        const uint32_t ph = (uint32_t)(s & 1);

        // warp 7: producer role. Poll peer flags + issue h(s) bulk FIRST, so the
        // transfer overlaps everyone's x-gemm. Safe: all warps finished the
        // previous h-gemm before step s-1's publish-__syncthreads.
        if (kq8 == 7) {
            if (lane < GRPBLK) {
                const int* fp = &g_flag[gid][lane][0];
                int v = ld_acquire(fp);
                while (v < s + 1) {
                    __nanosleep(20);
                    v = ld_acquire(fp);
                }
            }
            __syncwarp();
            if (lane == 0) {
                MBAR_EXPECT(mbh_b, 16384u);
                bulk_g2s(hx_b + (uint32_t)(DD * 16 * 4),
                         &g_hb[dir][p][bgrp][0][0], 16384u, mbh_b);
            }
        }

        mbar_wait(mbx_b, ph);               // x(s) landed

        unsigned long long acc[16];
        #pragma unroll
        for (int i = 0; i < 16; ++i) acc[i] = 0ull;

        // x-half: overlaps the in-flight h bulk + peer skew
        gemm_phase<32>(acc, hp_x, wp_x);

        // h(s) should already be resident; near-zero wait
        mbar_wait(mbh_b, ph);

        // h-half
        gemm_phase<32>(acc, hp_h, wp_h);

        // publish k-split partials: red[kq8][row][pr][b16] as u64-pair stores
        #pragma unroll
        for (int rg = 0; rg < 2; ++rg)
            #pragma unroll
            for (int pr = 0; pr < 2; ++pr)
                #pragma unroll
                for (int bp = 0; bp < 2; ++bp) {
                    int row = nl + rg * 8;
                    ulonglong2 v;
                    v.x = acc[rg * 8 + pr * 4 + bp * 2 + 0];
                    v.y = acc[rg * 8 + pr * 4 + bp * 2 + 1];
                    *(ulonglong2*)&red[(((kq8 * 16 + row) * 2 + pr) * 16)
                                       + bgq * 4 + bp * 2] = v;
                }
        __syncthreads();   // all warps done with gemm + hx regions

        // prefetch x(s+1): one bulk; overlaps epilogue + flag post + skew
        if (s + 1 < TT && tid == 0) {
            MBAR_EXPECT(mbx_b, 16384u);
            bulk_g2s(hx_b, &g_xt[dir][s + 1][bgrp][0][0], 16384u, mbx_b);
        }

        // epilogue: reduce 8 k-groups, gates, cell update (1 cell per thread)
        {
            unsigned long long s01 = 0ull, s23 = 0ull;
            #pragma unroll
            for (int q = 0; q < 8; ++q) {
                s01 = addf2(s01, red[((q * 16 + nl2) * 2 + 0) * 16 + bl]);
                s23 = addf2(s23, red[((q * 16 + nl2) * 2 + 1) * 16 + bl]);
            }
            float pi, pf, pg, po;
            unpack2(s01, pi, pf);
            unpack2(s23, pg, po);
            pi += bsv[nl2 * 4 + 0];
            pf += bsv[nl2 * 4 + 1];
            pg += bsv[nl2 * 4 + 2];
            po += bsv[nl2 * 4 + 3];

            float si = fsig(pi), sf = fsig(pf), tg = ftanh(pg), so = fsig(po);
            cth = sf * cth + si * tg;
            float hval = so * ftanh(cth);

            g_hb[dir][p ^ 1][bgrp][n][bl] = hval;   // non-dup store

            __syncthreads();        // all h writes done before the release-store
            if (tid == 0) st_release(&g_flag[gid][nc][0], s + 2);

            if (s < L) {
                const int t = dir ? (L - 1 - s) : s;
                out[((size_t)myb * TT + t) * (2 * HH) + dir * HH + n] = hval;
            }
        }
        p ^= 1;
    }

    // final barrier, then reset flags for the next graph replay
    global_barrier(tid);
    if (tid == 0) *((volatile int*)&g_flag[gid][nc][0]) = 0;
}

extern "C" void kernel_launch(void* const* d_in, const int* in_sizes, int n_in,
                              void* d_out, int out_size) {
    const float* x     = (const float*)d_in[0];
    const int*   lens  = (const int*)  d_in[1];
    const float* Wih_f = (const float*)d_in[2];
    const float* Whh_f = (const float*)d_in[3];
    const float* bih_f = (const float*)d_in[4];
    const float* bhh_f = (const float*)d_in[5];
    const float* Wih_b = (const float*)d_in[6];
    const float* Whh_b = (const float*)d_in[7];
    const float* bih_b = (const float*)d_in[8];
    const float* bhh_b = (const float*)d_in[9];
    float* out = (float*)d_out;

    // zero the padded/masked region (output beyond input_length must be 0)
    cudaMemsetAsync(out, 0, (size_t)out_size * sizeof(float), 0);

    const size_t smem_bytes = (size_t)SMEM_FLOATS * sizeof(float);
    cudaFuncSetAttribute(bilstm_kernel,
                         cudaFuncAttributeMaxDynamicSharedMemorySize, (int)smem_bytes);

    bilstm_kernel<<<NBLK, NTHR, smem_bytes>>>(x, lens, Wih_f, Whh_f, bih_f, bhh_f,
                                              Wih_b, Whh_b, bih_b, bhh_b, out);
}